// round 10
// baseline (speedup 1.0000x reference)
#include <cuda_runtime.h>
#include <cuda_bf16.h>

#define GROUPS   512
#define ARITY    2
#define OUT_DIM  16
#define GPB      128   // groups per block (128 groups * 2 halves = 256 threads)
#define GRID_Y   128   // batch chunks -> 64 rows per block (batch 8192)
#define CHUNK    8     // X-load prefetch depth (MLP per thread)

typedef unsigned long long u64;

// Pack a scalar weight into both lanes of an f32x2 register.
__device__ __forceinline__ u64 pack2(float w) {
    u64 r;
    asm("mov.b64 %0, {%1, %1};" : "=l"(r) : "r"(__float_as_uint(w)));
    return r;
}
#define MUL2(d, a, b)    asm("mul.rn.f32x2 %0, %1, %2;"     : "=l"(d) : "l"(a), "l"(b))
#define FMA2(d, a, b, c) asm("fma.rn.f32x2 %0, %1, %2, %3;" : "=l"(d) : "l"(a), "l"(b), "l"(c))
// 128-bit streaming store of two packed f32x2 lanes
#define STCS2(p, a, b) \
    asm volatile("st.global.cs.v2.b64 [%0], {%1, %2};" :: "l"(p), "l"(a), "l"(b) : "memory")

// out[b, g*16 + d] = bilinear interp of params[g, 0..3, d] at
// (u, v) = ((clip(x0,-1,1)+1)/2, (clip(x1,-1,1)+1)/2).
// Exact algebraic collapse of the midpoint-expanded 3x3 hat-basis contraction:
// inserted midpoints are exact averages, so the 3-pt hat interpolation on each
// axis is the straight line lerp(lo, hi, t/2).
__global__ __launch_bounds__(256) void corner_bilinear_kernel(
    const float* __restrict__ X,
    const float* __restrict__ params,
    float* __restrict__ out,
    int batch, int rows_per_block)
{
    const int tid = threadIdx.x;
    const int h   = tid & 1;          // half-group: dims [8h, 8h+8)
    const int gl  = tid >> 1;         // local group 0..127
    const int g   = blockIdx.x * GPB + gl;
    const int b0  = blockIdx.y * rows_per_block;

    // params[g, c, d]: float4 index = g*16 + c*4 + h*2 + {0,1}; corner c = 2*c0+c1
    const float4* Pf = reinterpret_cast<const float4*>(params)
                     + (size_t)g * 16 + h * 2;
    u64 Pc[4][4];   // [corner][f32x2 lane], 8 dims per thread
    #pragma unroll
    for (int c = 0; c < 4; ++c) {
        union { float4 f; u64 u[2]; } t;
        t.f = __ldg(Pf + c * 4 + 0);
        Pc[c][0] = t.u[0]; Pc[c][1] = t.u[1];
        t.f = __ldg(Pf + c * 4 + 1);
        Pc[c][2] = t.u[0]; Pc[c][3] = t.u[1];
    }

    // X row = GROUPS float2's; group g uses X[b, 2g], X[b, 2g+1]
    const float2* Xp = reinterpret_cast<const float2*>(X) + (size_t)b0 * GROUPS + g;
    // output base for this thread: float offset b*8192 + (2g+h)*8
    float* Ob = out + (size_t)b0 * (GROUPS * OUT_DIM)
              + ((size_t)g * 2 + h) * 8;
    const size_t row_stride = GROUPS * OUT_DIM;  // floats per batch row

    const int rows = min(rows_per_block, batch - b0);

    int i0 = 0;
    for (; i0 + CHUNK <= rows; i0 += CHUNK) {
        float2 uv[CHUNK];
        // front-batched loads: MLP_p1 = CHUNK hides DRAM latency
        #pragma unroll
        for (int j = 0; j < CHUNK; ++j) {
            const float2 xv = __ldg(Xp + (size_t)(i0 + j) * GROUPS);
            uv[j].x = (fminf(fmaxf(xv.x, -1.0f), 1.0f) + 1.0f) * 0.5f;
            uv[j].y = (fminf(fmaxf(xv.y, -1.0f), 1.0f) + 1.0f) * 0.5f;
        }

        #pragma unroll
        for (int j = 0; j < CHUNK; ++j) {
            const float u = uv[j].x;
            const float v = uv[j].y;
            const float wD = u * v;              // uv        -> corner (1,1)
            const float wC = u - wD;             // u(1-v)    -> (1,0)
            const float wB = v - wD;             // (1-u)v    -> (0,1)
            const float wA = 1.0f - u - v + wD;  // (1-u)(1-v)-> (0,0)

            const u64 wAp = pack2(wA), wBp = pack2(wB);
            const u64 wCp = pack2(wC), wDp = pack2(wD);

            u64 a0, a1, a2, a3;
            MUL2(a0, wAp, Pc[0][0]); MUL2(a1, wAp, Pc[0][1]);
            MUL2(a2, wAp, Pc[0][2]); MUL2(a3, wAp, Pc[0][3]);
            FMA2(a0, wBp, Pc[1][0], a0); FMA2(a1, wBp, Pc[1][1], a1);
            FMA2(a2, wBp, Pc[1][2], a2); FMA2(a3, wBp, Pc[1][3], a3);
            FMA2(a0, wCp, Pc[2][0], a0); FMA2(a1, wCp, Pc[2][1], a1);
            FMA2(a2, wCp, Pc[2][2], a2); FMA2(a3, wCp, Pc[2][3], a3);
            FMA2(a0, wDp, Pc[3][0], a0); FMA2(a1, wDp, Pc[3][1], a1);
            FMA2(a2, wDp, Pc[3][2], a2); FMA2(a3, wDp, Pc[3][3], a3);

            float* p = Ob + (size_t)(i0 + j) * row_stride;
            // two 128-bit streaming stores (evict-first; output >> L2)
            STCS2(p,     a0, a1);
            STCS2(p + 4, a2, a3);
        }
    }
    // scalar tail (only if batch % (GRID_Y*CHUNK) != 0)
    for (; i0 < rows; ++i0) {
        const float2 xv = __ldg(Xp + (size_t)i0 * GROUPS);
        const float u = (fminf(fmaxf(xv.x, -1.0f), 1.0f) + 1.0f) * 0.5f;
        const float v = (fminf(fmaxf(xv.y, -1.0f), 1.0f) + 1.0f) * 0.5f;
        const float wD = u * v;
        const float wC = u - wD;
        const float wB = v - wD;
        const float wA = 1.0f - u - v + wD;

        union { u64 u2; float f[2]; } pa, pb, pc, pd;
        float* p = Ob + (size_t)i0 * row_stride;
        #pragma unroll
        for (int k = 0; k < 4; ++k) {
            pa.u2 = Pc[0][k]; pb.u2 = Pc[1][k]; pc.u2 = Pc[2][k]; pd.u2 = Pc[3][k];
            #pragma unroll
            for (int l = 0; l < 2; ++l) {
                p[k * 2 + l] = fmaf(wA, pa.f[l],
                               fmaf(wB, pb.f[l],
                               fmaf(wC, pc.f[l], wD * pd.f[l])));
            }
        }
    }
}

extern "C" void kernel_launch(void* const* d_in, const int* in_sizes, int n_in,
                              void* d_out, int out_size)
{
    // Identify X vs params by element count (X = B*1024, params = 512*4*16 = 32768)
    const float* X;
    const float* params;
    int szX;
    if (in_sizes[0] > in_sizes[1]) {
        X = (const float*)d_in[0]; params = (const float*)d_in[1]; szX = in_sizes[0];
    } else {
        X = (const float*)d_in[1]; params = (const float*)d_in[0]; szX = in_sizes[1];
    }
    const int batch = szX / (GROUPS * ARITY);
    const int rows_per_block = (batch + GRID_Y - 1) / GRID_Y;

    dim3 block(256);
    dim3 grid(GROUPS / GPB, GRID_Y);
    corner_bilinear_kernel<<<grid, block>>>(X, params, (float*)d_out,
                                            batch, rows_per_block);
}

// round 12
// speedup vs baseline: 1.5661x; 1.5661x over previous
#include <cuda_runtime.h>
#include <cuda_bf16.h>

#define GROUPS   512
#define ARITY    2
#define OUT_DIM  16
#define GPB      64    // groups per block (64 groups * 4 dim-quads = 256 threads)
#define GRID_Y   128   // batch chunks -> 64 rows per block (batch 8192)
#define CHUNK    8     // X-load prefetch depth (MLP per thread)

// out[b, g*16 + d] = bilinear interp of params[g, 0..3, d] at
// (u, v) = ((clip(x0,-1,1)+1)/2, (clip(x1,-1,1)+1)/2).
// Exact algebraic collapse of the midpoint-expanded 3x3 hat-basis contraction:
// inserted midpoints are exact averages, so the 3-pt hat interpolation on each
// axis is the straight line lerp(lo, hi, t/2).
__global__ __launch_bounds__(256, 6) void corner_bilinear_kernel(
    const float* __restrict__ X,
    const float* __restrict__ params,
    float* __restrict__ out,
    int batch, int rows_per_block)
{
    const int tid = threadIdx.x;
    const int q   = tid & 3;          // dim-quad 0..3 (4 floats each)
    const int gl  = tid >> 2;         // local group 0..63
    const int g   = blockIdx.x * GPB + gl;
    const int b0  = blockIdx.y * rows_per_block;

    // params[g, c, d]: float4 index = g*16 + c*4 + q  (corner c = 2*c0 + c1)
    const float4* P = reinterpret_cast<const float4*>(params) + (size_t)g * 16 + q;
    const float4 p0 = __ldg(P + 0);   // (0,0) -> (1-u)(1-v)
    const float4 p1 = __ldg(P + 4);   // (0,1) -> (1-u)v
    const float4 p2 = __ldg(P + 8);   // (1,0) -> u(1-v)
    const float4 p3 = __ldg(P + 12);  // (1,1) -> uv

    // X row = GROUPS float2's; group g uses X[b, 2g], X[b, 2g+1]
    const float2* Xp = reinterpret_cast<const float2*>(X) + (size_t)b0 * GROUPS + g;
    // out row = GROUPS*OUT_DIM/4 = 2048 float4's
    float4* O = reinterpret_cast<float4*>(out)
              + (size_t)b0 * (GROUPS * OUT_DIM / 4) + (size_t)g * 4 + q;

    const int rows = min(rows_per_block, batch - b0);

    int i0 = 0;
    // fast path: full chunks (batch=8192, GRID_Y=128 -> rows=64, always exact)
    for (; i0 + CHUNK <= rows; i0 += CHUNK) {
        float2 uv[CHUNK];
        // front-batched loads: MLP_p1 = CHUNK, hides DRAM latency;
        // clip folded in so only post-clip values stay live (register budget)
        #pragma unroll
        for (int j = 0; j < CHUNK; ++j) {
            const float2 xv = __ldg(Xp + (size_t)(i0 + j) * GROUPS);
            uv[j].x = (fminf(fmaxf(xv.x, -1.0f), 1.0f) + 1.0f) * 0.5f;
            uv[j].y = (fminf(fmaxf(xv.y, -1.0f), 1.0f) + 1.0f) * 0.5f;
        }

        #pragma unroll
        for (int j = 0; j < CHUNK; ++j) {
            const float u = uv[j].x;
            const float v = uv[j].y;

            const float wD = u * v;              // uv
            const float wC = u - wD;             // u(1-v)
            const float wB = v - wD;             // (1-u)v
            const float wA = 1.0f - u - v + wD;  // (1-u)(1-v)

            float4 o;
            o.x = fmaf(wA, p0.x, fmaf(wB, p1.x, fmaf(wC, p2.x, wD * p3.x)));
            o.y = fmaf(wA, p0.y, fmaf(wB, p1.y, fmaf(wC, p2.y, wD * p3.y)));
            o.z = fmaf(wA, p0.z, fmaf(wB, p1.z, fmaf(wC, p2.z, wD * p3.z)));
            o.w = fmaf(wA, p0.w, fmaf(wB, p1.w, fmaf(wC, p2.w, wD * p3.w)));

            // streaming store: 256 MiB output >> L2, evict early
            __stcs(O + (size_t)(i0 + j) * (GROUPS * OUT_DIM / 4), o);
        }
    }
    // tail (only if batch % (GRID_Y*CHUNK) != 0)
    for (; i0 < rows; ++i0) {
        const float2 xv = __ldg(Xp + (size_t)i0 * GROUPS);
        const float u = (fminf(fmaxf(xv.x, -1.0f), 1.0f) + 1.0f) * 0.5f;
        const float v = (fminf(fmaxf(xv.y, -1.0f), 1.0f) + 1.0f) * 0.5f;
        const float wD = u * v;
        const float wC = u - wD;
        const float wB = v - wD;
        const float wA = 1.0f - u - v + wD;
        float4 o;
        o.x = fmaf(wA, p0.x, fmaf(wB, p1.x, fmaf(wC, p2.x, wD * p3.x)));
        o.y = fmaf(wA, p0.y, fmaf(wB, p1.y, fmaf(wC, p2.y, wD * p3.y)));
        o.z = fmaf(wA, p0.z, fmaf(wB, p1.z, fmaf(wC, p2.z, wD * p3.z)));
        o.w = fmaf(wA, p0.w, fmaf(wB, p1.w, fmaf(wC, p2.w, wD * p3.w)));
        __stcs(O + (size_t)i0 * (GROUPS * OUT_DIM / 4), o);
    }
}

extern "C" void kernel_launch(void* const* d_in, const int* in_sizes, int n_in,
                              void* d_out, int out_size)
{
    // Identify X vs params by element count (X = B*1024, params = 512*4*16 = 32768)
    const float* X;
    const float* params;
    int szX;
    if (in_sizes[0] > in_sizes[1]) {
        X = (const float*)d_in[0]; params = (const float*)d_in[1]; szX = in_sizes[0];
    } else {
        X = (const float*)d_in[1]; params = (const float*)d_in[0]; szX = in_sizes[1];
    }
    const int batch = szX / (GROUPS * ARITY);
    const int rows_per_block = (batch + GRID_Y - 1) / GRID_Y;

    dim3 block(256);
    dim3 grid(GROUPS / GPB, GRID_Y);
    corner_bilinear_kernel<<<grid, block>>>(X, params, (float*)d_out,
                                            batch, rows_per_block);
}

// round 13
// speedup vs baseline: 1.7131x; 1.0938x over previous
#include <cuda_runtime.h>
#include <cuda_bf16.h>

#define GROUPS   512
#define ARITY    2
#define OUT_DIM  16
#define GPB      64    // groups per block (64 groups * 4 dim-quads = 256 threads)
#define GRID_Y   92    // 8 x 92 = 736 blocks = one full wave at 5 blocks/SM x 148 SMs
#define CHUNK    8     // X-load prefetch depth (MLP per thread)

// out[b, g*16 + d] = bilinear interp of params[g, 0..3, d] at
// (u, v) = ((clip(x0,-1,1)+1)/2, (clip(x1,-1,1)+1)/2).
// Exact algebraic collapse of the midpoint-expanded 3x3 hat-basis contraction:
// inserted midpoints are exact averages, so the 3-pt hat interpolation on each
// axis is the straight line lerp(lo, hi, t/2).
__global__ __launch_bounds__(256) void corner_bilinear_kernel(
    const float* __restrict__ X,
    const float* __restrict__ params,
    float* __restrict__ out,
    int batch)
{
    const int tid = threadIdx.x;
    const int q   = tid & 3;          // dim-quad 0..3 (4 floats each)
    const int gl  = tid >> 2;         // local group 0..63
    const int g   = blockIdx.x * GPB + gl;

    // balanced batch partition: block y handles rows [b0, b1)
    const int yb  = blockIdx.y;
    const int b0  = (int)(((long long)yb     * batch) / GRID_Y);
    const int b1  = (int)(((long long)(yb+1) * batch) / GRID_Y);
    const int rows = b1 - b0;

    // params[g, c, d]: float4 index = g*16 + c*4 + q  (corner c = 2*c0 + c1)
    const float4* P = reinterpret_cast<const float4*>(params) + (size_t)g * 16 + q;
    const float4 p0 = __ldg(P + 0);   // (0,0) -> (1-u)(1-v)
    const float4 p1 = __ldg(P + 4);   // (0,1) -> (1-u)v
    const float4 p2 = __ldg(P + 8);   // (1,0) -> u(1-v)
    const float4 p3 = __ldg(P + 12);  // (1,1) -> uv

    // X row = GROUPS float2's; group g uses X[b, 2g], X[b, 2g+1]
    const float2* Xp = reinterpret_cast<const float2*>(X) + (size_t)b0 * GROUPS + g;
    // out row = GROUPS*OUT_DIM/4 = 2048 float4's
    float4* O = reinterpret_cast<float4*>(out)
              + (size_t)b0 * (GROUPS * OUT_DIM / 4) + (size_t)g * 4 + q;

    int i0 = 0;
    for (; i0 + CHUNK <= rows; i0 += CHUNK) {
        float2 uv[CHUNK];
        // front-batched loads: MLP_p1 = CHUNK, hides DRAM latency;
        // clip folded in so only post-clip values stay live
        #pragma unroll
        for (int j = 0; j < CHUNK; ++j) {
            const float2 xv = __ldg(Xp + (size_t)(i0 + j) * GROUPS);
            uv[j].x = (fminf(fmaxf(xv.x, -1.0f), 1.0f) + 1.0f) * 0.5f;
            uv[j].y = (fminf(fmaxf(xv.y, -1.0f), 1.0f) + 1.0f) * 0.5f;
        }

        #pragma unroll
        for (int j = 0; j < CHUNK; ++j) {
            const float u = uv[j].x;
            const float v = uv[j].y;

            const float wD = u * v;              // uv
            const float wC = u - wD;             // u(1-v)
            const float wB = v - wD;             // (1-u)v
            const float wA = 1.0f - u - v + wD;  // (1-u)(1-v)

            float4 o;
            o.x = fmaf(wA, p0.x, fmaf(wB, p1.x, fmaf(wC, p2.x, wD * p3.x)));
            o.y = fmaf(wA, p0.y, fmaf(wB, p1.y, fmaf(wC, p2.y, wD * p3.y)));
            o.z = fmaf(wA, p0.z, fmaf(wB, p1.z, fmaf(wC, p2.z, wD * p3.z)));
            o.w = fmaf(wA, p0.w, fmaf(wB, p1.w, fmaf(wC, p2.w, wD * p3.w)));

            // streaming store: 256 MiB output >> L2, evict early
            __stcs(O + (size_t)(i0 + j) * (GROUPS * OUT_DIM / 4), o);
        }
    }
    // tail: rows % CHUNK leftover (89/90-row slices -> 1-2 scalar rows)
    for (; i0 < rows; ++i0) {
        const float2 xv = __ldg(Xp + (size_t)i0 * GROUPS);
        const float u = (fminf(fmaxf(xv.x, -1.0f), 1.0f) + 1.0f) * 0.5f;
        const float v = (fminf(fmaxf(xv.y, -1.0f), 1.0f) + 1.0f) * 0.5f;
        const float wD = u * v;
        const float wC = u - wD;
        const float wB = v - wD;
        const float wA = 1.0f - u - v + wD;
        float4 o;
        o.x = fmaf(wA, p0.x, fmaf(wB, p1.x, fmaf(wC, p2.x, wD * p3.x)));
        o.y = fmaf(wA, p0.y, fmaf(wB, p1.y, fmaf(wC, p2.y, wD * p3.y)));
        o.z = fmaf(wA, p0.z, fmaf(wB, p1.z, fmaf(wC, p2.z, wD * p3.z)));
        o.w = fmaf(wA, p0.w, fmaf(wB, p1.w, fmaf(wC, p2.w, wD * p3.w)));
        __stcs(O + (size_t)i0 * (GROUPS * OUT_DIM / 4), o);
    }
}

extern "C" void kernel_launch(void* const* d_in, const int* in_sizes, int n_in,
                              void* d_out, int out_size)
{
    // Identify X vs params by element count (X = B*1024, params = 512*4*16 = 32768)
    const float* X;
    const float* params;
    int szX;
    if (in_sizes[0] > in_sizes[1]) {
        X = (const float*)d_in[0]; params = (const float*)d_in[1]; szX = in_sizes[0];
    } else {
        X = (const float*)d_in[1]; params = (const float*)d_in[0]; szX = in_sizes[1];
    }
    const int batch = szX / (GROUPS * ARITY);

    dim3 block(256);
    dim3 grid(GROUPS / GPB, GRID_Y);
    corner_bilinear_kernel<<<grid, block>>>(X, params, (float*)d_out, batch);
}